// round 2
// baseline (speedup 1.0000x reference)
#include <cuda_runtime.h>
#include <math.h>

#define BD   2
#define CINC 64
#define COUTC 64
#define HH   192
#define WW   192
#define DGC  8
#define CGC  8
#define KKC  9
#define HWC  (HH*WW)

// ---------------- scratch (static device globals; no allocation allowed) ----
__device__ float g_x0t[BD*CINC*HWC];        // x0 repacked [B][DG][H][W][CG]
__device__ float g_pdy[BD*DGC*KKC*HWC];     // final dy per (b, g*9+k, y, x)
__device__ float g_pdx[BD*DGC*KKC*HWC];
__device__ float g_pm [BD*DGC*KKC*HWC];

// ---------------- kernel T: repack x0 so CG=8 channels are contiguous ------
__global__ void k_transpose(const float* __restrict__ x0) {
    int m = blockIdx.x * blockDim.x + threadIdx.x;
    if (m >= BD*CINC*HWC) return;
    int x   = m % WW;
    int y   = (m / WW) % HH;
    int cin = (m / HWC) % CINC;
    int b   = m / (HWC*CINC);
    int g = cin >> 3, c = cin & 7;
    g_x0t[(((b*DGC + g)*HWC) + y*WW + x)*CGC + c] = x0[m];
}

// ---------------- kernel C: offset/mask conv (64 -> 216) + transforms ------
// grid (144, B), 256 threads, 16x16 pixel tile.
// smem: xs[64][18][18] (82944 B) + ws[576][28] (64512 B) = 147456 B
__global__ void k_offsets(const float* __restrict__ x1,
                          const float* __restrict__ com_w,
                          const float* __restrict__ com_b,
                          const float* __restrict__ pre_off,
                          const float* __restrict__ pre_sim) {
    extern __shared__ float sm[];
    float* xs = sm;              // [cin][r][cc], 64*324
    float* ws = sm + 64*324;     // [t][28] padded, t = cin*9 + tap

    int b    = blockIdx.y;
    int tile = blockIdx.x;
    int ty0  = (tile / 12) * 16;
    int tx0  = (tile % 12) * 16;
    int tid  = threadIdx.x;

    // load input tile with halo (zero-padded at image border)
    for (int m = tid; m < 64*324; m += 256) {
        int cin = m / 324;
        int r   = (m % 324) / 18;
        int cc  = m % 18;
        int gy = ty0 - 1 + r, gx = tx0 - 1 + cc;
        float v = 0.f;
        if (gy >= 0 && gy < HH && gx >= 0 && gx < WW)
            v = x1[((b*CINC + cin)*HH + gy)*WW + gx];
        xs[m] = v;
    }

    int ty = tid >> 4, tx = tid & 15;
    int y = ty0 + ty, x = tx0 + tx;

    // 9 chunks of 8 taps; per chunk the 24 conv channels {2i,2i+1,144+i}
    for (int chunk = 0; chunk < 9; chunk++) {
        int i0 = chunk * 8;
        __syncthreads();   // first iter: xs ready; later: prev compute done before ws overwrite
        for (int m = tid; m < 24*576; m += 256) {
            int j = m / 576;
            int t = m % 576;
            int ch = (j < 16) ? (2*i0 + j) : (144 + i0 + (j - 16));
            ws[t*28 + j] = com_w[ch*576 + t];
        }
        __syncthreads();

        float acc[24];
        #pragma unroll
        for (int j = 0; j < 24; j++) acc[j] = 0.f;

        for (int cin = 0; cin < 64; cin++) {
            #pragma unroll
            for (int ki = 0; ki < 3; ki++) {
                #pragma unroll
                for (int kj = 0; kj < 3; kj++) {
                    float xv = xs[cin*324 + (ty + ki)*18 + (tx + kj)];
                    const float4* w4 =
                        reinterpret_cast<const float4*>(&ws[(cin*9 + ki*3 + kj)*28]);
                    #pragma unroll
                    for (int q = 0; q < 6; q++) {
                        float4 w = w4[q];
                        acc[q*4+0] = fmaf(xv, w.x, acc[q*4+0]);
                        acc[q*4+1] = fmaf(xv, w.y, acc[q*4+1]);
                        acc[q*4+2] = fmaf(xv, w.z, acc[q*4+2]);
                        acc[q*4+3] = fmaf(xv, w.w, acc[q*4+3]);
                    }
                }
            }
        }

        // epilogue: tanh / sigmoid / pre-offset / pre-sim fusion
        #pragma unroll
        for (int j = 0; j < 8; j++) {
            int i = i0 + j;            // tap index = g*9 + k
            int k = i % 9;
            float o1 = acc[2*j]     + com_b[2*i];
            float o2 = acc[2*j + 1] + com_b[2*i + 1];
            float mr = acc[16 + j]  + com_b[144 + i];
            int pidx = (((b*KKC + k)*HH + y)*WW + x) * 2;
            // pre_r: dy (comp0 of off) += pre_offset[...,1]; dx += pre_offset[...,0]
            float dy = 10.f * tanhf(o1) + pre_off[pidx + 1];
            float dx = 10.f * tanhf(o2) + pre_off[pidx + 0];
            int idx = ((b*72 + i)*HH + y)*WW + x;
            float sim = pre_sim[idx];
            float msk = 1.f / (1.f + expf(-mr * sim));
            g_pdy[idx] = dy;
            g_pdx[idx] = dx;
            g_pm [idx] = msk;
        }
    }
}

// ---------------- kernel S: bilinear sample + dense 576-term reduce --------
// grid (144, B), 256 threads, 16x16 pixel tile, 64 accumulators/thread.
// smem: ws[72][8][64] = 36864 floats = 147456 B
__global__ void k_sample(const float* __restrict__ weight,
                         const float* __restrict__ bias,
                         float* __restrict__ out) {
    extern __shared__ float ws[];
    int b    = blockIdx.y;
    int tile = blockIdx.x;
    int ty0  = (tile / 12) * 16;
    int tx0  = (tile % 12) * 16;
    int tid  = threadIdx.x;

    // weight[o][cin][kk] -> ws[(g*9+k)*8 + c][o]
    for (int m = tid; m < 72*8*64; m += 256) {
        int o = m & 63;
        int c = (m >> 6) & 7;
        int i = m >> 9;             // g*9 + k
        int k = i % 9, g = i / 9;
        ws[m] = weight[(o*CINC + g*8 + c)*KKC + k];
    }
    __syncthreads();

    int ty = tid >> 4, tx = tid & 15;
    int y = ty0 + ty, x = tx0 + tx;

    float acc[64];
    #pragma unroll
    for (int o = 0; o < 64; o++) acc[o] = 0.f;

    for (int g = 0; g < DGC; g++) {
        const float* xb = g_x0t + (size_t)(b*DGC + g) * HWC * CGC;
        for (int k = 0; k < KKC; k++) {
            int i = g*9 + k;
            int idx = ((b*72 + i)*HH + y)*WW + x;
            float dy = g_pdy[idx];
            float dx = g_pdx[idx];
            float mk = g_pm [idx];
            float py = (float)(y - 1 + k/3) + dy;
            float px = (float)(x - 1 + k%3) + dx;
            float y0f = floorf(py), x0f = floorf(px);
            float ly = py - y0f,   lx = px - x0f;
            int iy0 = (int)y0f, ix0 = (int)x0f;

            float sv[8];
            #pragma unroll
            for (int c = 0; c < 8; c++) sv[c] = 0.f;

            #pragma unroll
            for (int cy = 0; cy < 2; cy++) {
                int yy = iy0 + cy;
                if (yy < 0 || yy >= HH) continue;
                float wy = cy ? ly : (1.f - ly);
                #pragma unroll
                for (int cx = 0; cx < 2; cx++) {
                    int xx = ix0 + cx;
                    if (xx < 0 || xx >= WW) continue;
                    float wgt = wy * (cx ? lx : (1.f - lx));
                    const float4* p =
                        reinterpret_cast<const float4*>(xb + (size_t)(yy*WW + xx)*CGC);
                    float4 v0 = p[0];
                    float4 v1 = p[1];
                    sv[0] = fmaf(wgt, v0.x, sv[0]);
                    sv[1] = fmaf(wgt, v0.y, sv[1]);
                    sv[2] = fmaf(wgt, v0.z, sv[2]);
                    sv[3] = fmaf(wgt, v0.w, sv[3]);
                    sv[4] = fmaf(wgt, v1.x, sv[4]);
                    sv[5] = fmaf(wgt, v1.y, sv[5]);
                    sv[6] = fmaf(wgt, v1.z, sv[6]);
                    sv[7] = fmaf(wgt, v1.w, sv[7]);
                }
            }

            const float* wrow = ws + i*512;
            #pragma unroll
            for (int c = 0; c < 8; c++) {
                float s = sv[c] * mk;
                const float4* wp = reinterpret_cast<const float4*>(wrow + c*64);
                #pragma unroll
                for (int q = 0; q < 16; q++) {
                    float4 w = wp[q];
                    acc[q*4+0] = fmaf(s, w.x, acc[q*4+0]);
                    acc[q*4+1] = fmaf(s, w.y, acc[q*4+1]);
                    acc[q*4+2] = fmaf(s, w.z, acc[q*4+2]);
                    acc[q*4+3] = fmaf(s, w.w, acc[q*4+3]);
                }
            }
        }
    }

    #pragma unroll
    for (int o = 0; o < 64; o++)
        out[((b*COUTC + o)*HH + y)*WW + x] = acc[o] + bias[o];
}

// ---------------- launch ----------------------------------------------------
extern "C" void kernel_launch(void* const* d_in, const int* in_sizes, int n_in,
                              void* d_out, int out_size) {
    const float* x0      = (const float*)d_in[0];
    const float* x1      = (const float*)d_in[1];
    const float* pre_off = (const float*)d_in[2];
    const float* pre_sim = (const float*)d_in[3];
    const float* weight  = (const float*)d_in[4];
    const float* bias    = (const float*)d_in[5];
    const float* com_w   = (const float*)d_in[6];
    const float* com_b   = (const float*)d_in[7];
    float* out = (float*)d_out;

    // >48KB dynamic smem opt-in (host-side attribute set; idempotent, capture-safe)
    cudaFuncSetAttribute(k_offsets, cudaFuncAttributeMaxDynamicSharedMemorySize, 147456);
    cudaFuncSetAttribute(k_sample,  cudaFuncAttributeMaxDynamicSharedMemorySize, 147456);

    int total = BD*CINC*HWC;
    k_transpose<<<(total + 255) / 256, 256>>>(x0);

    dim3 grid(144, BD);
    k_offsets<<<grid, 256, 147456>>>(x1, com_w, com_b, pre_off, pre_sim);
    k_sample <<<grid, 256, 147456>>>(weight, bias, out);
}

// round 3
// speedup vs baseline: 1.4122x; 1.4122x over previous
#include <cuda_runtime.h>
#include <math.h>

#define BD   2
#define CINC 64
#define COUTC 64
#define HH   192
#define WW   192
#define DGC  8
#define CGC  8
#define KKC  9
#define HWC  (HH*WW)

typedef unsigned long long u64;

__device__ __forceinline__ u64 pk2(float v) {
    u64 r; asm("mov.b64 %0, {%1,%1};" : "=l"(r) : "f"(v)); return r;
}
__device__ __forceinline__ void fma2(u64 &d, u64 a, u64 b) {
    asm("fma.rn.f32x2 %0, %1, %2, %0;" : "+l"(d) : "l"(a), "l"(b));
}
__device__ __forceinline__ float lo32(u64 v) { return __uint_as_float((unsigned)v); }
__device__ __forceinline__ float hi32(u64 v) { return __uint_as_float((unsigned)(v >> 32)); }

// ---------------- scratch ---------------------------------------------------
__device__ float  g_x0t[BD*CINC*HWC];          // x0 repacked [B][DG][H*W][CG]
__device__ float4 g_par[BD*DGC*KKC*HWC];       // (dy, dx, mask, 0) per (b, g*9+k, y, x)

// ---------------- kernel T: repack x0 (8ch contiguous) ----------------------
__global__ void k_transpose(const float* __restrict__ x0) {
    int m = blockIdx.x * blockDim.x + threadIdx.x;
    if (m >= BD*DGC*HWC) return;
    int yx = m % HWC;
    int g  = (m / HWC) % DGC;
    int b  = m / (HWC*DGC);
    const float* src = x0 + ((size_t)(b*CINC + g*8)*HWC) + yx;
    float4 a, c;
    a.x = src[0*HWC]; a.y = src[1*HWC]; a.z = src[2*HWC]; a.w = src[3*HWC];
    c.x = src[4*HWC]; c.y = src[5*HWC]; c.z = src[6*HWC]; c.w = src[7*HWC];
    float4* dst = reinterpret_cast<float4*>(g_x0t + (size_t)m * 8);
    dst[0] = a; dst[1] = c;
}

// ---------------- kernel C: offset/mask conv (64 -> 216) + transforms -------
// grid (72, B), 256 threads, 32x16 pixel tile, 2 px per thread (rows y, y+16).
// smem: xs[64][34][18] (156672 B) + ws[576][28] (64512 B) = 221184 B
__global__ void __launch_bounds__(256, 1)
k_offsets(const float* __restrict__ x1,
          const float* __restrict__ com_w,
          const float* __restrict__ com_b,
          const float* __restrict__ pre_off,
          const float* __restrict__ pre_sim) {
    extern __shared__ float sm[];
    float* xs = sm;              // [cin][34][18]
    float* ws = sm + 64*612;     // [t][28], t = cin*9 + tap

    int b    = blockIdx.y;
    int tile = blockIdx.x;
    int ty0  = (tile / 12) * 32;
    int tx0  = (tile % 12) * 16;
    int tid  = threadIdx.x;

    // load input tile with halo (zero-padded)
    for (int m = tid; m < 64*612; m += 256) {
        int cin = m / 612;
        int r   = (m % 612) / 18;
        int cc  = m % 18;
        int gy = ty0 - 1 + r, gx = tx0 - 1 + cc;
        float v = 0.f;
        if (gy >= 0 && gy < HH && gx >= 0 && gx < WW)
            v = x1[((b*CINC + cin)*HH + gy)*WW + gx];
        xs[m] = v;
    }

    int ty = tid >> 4, tx = tid & 15;
    int y0p = ty0 + ty;            // pixel 0 row
    int y1p = y0p + 16;            // pixel 1 row
    int x   = tx0 + tx;

    for (int chunk = 0; chunk < 9; chunk++) {
        int i0 = chunk * 8;
        __syncthreads();
        for (int m = tid; m < 24*576; m += 256) {
            int j = m / 576;
            int t = m % 576;
            int ch = (j < 16) ? (2*i0 + j) : (144 + i0 + (j - 16));
            ws[t*28 + j] = com_w[ch*576 + t];
        }
        __syncthreads();

        u64 acc0[12], acc1[12];
        #pragma unroll
        for (int q = 0; q < 12; q++) { acc0[q] = 0ull; acc1[q] = 0ull; }

        for (int cin = 0; cin < 64; cin++) {
            #pragma unroll
            for (int ki = 0; ki < 3; ki++) {
                #pragma unroll
                for (int kj = 0; kj < 3; kj++) {
                    float xa = xs[cin*612 + (ty + ki)*18 + (tx + kj)];
                    float xb = xs[cin*612 + (ty + 16 + ki)*18 + (tx + kj)];
                    u64 xva = pk2(xa), xvb = pk2(xb);
                    const ulonglong2* wp =
                        reinterpret_cast<const ulonglong2*>(&ws[(cin*9 + ki*3 + kj)*28]);
                    #pragma unroll
                    for (int q = 0; q < 6; q++) {
                        ulonglong2 w = wp[q];
                        fma2(acc0[2*q],   xva, w.x);
                        fma2(acc0[2*q+1], xva, w.y);
                        fma2(acc1[2*q],   xvb, w.x);
                        fma2(acc1[2*q+1], xvb, w.y);
                    }
                }
            }
        }

        // epilogue for both pixels
        #pragma unroll
        for (int j = 0; j < 8; j++) {
            int i = i0 + j;            // tap index = g*9 + k
            int k = i % 9;
            float b1 = com_b[2*i], b2 = com_b[2*i+1], b3 = com_b[144 + i];
            #pragma unroll
            for (int p = 0; p < 2; p++) {
                int y = p ? y1p : y0p;
                const u64* acc = p ? acc1 : acc0;
                float o1 = lo32(acc[j]) + b1;                          // ch 2j
                float o2 = hi32(acc[j]) + b2;                          // ch 2j+1
                u64 am = acc[8 + (j >> 1)];
                float mr = ((j & 1) ? hi32(am) : lo32(am)) + b3;       // ch 16+j
                int pidx = (((b*KKC + k)*HH + y)*WW + x) * 2;
                float dy = 10.f * tanhf(o1) + pre_off[pidx + 1];
                float dx = 10.f * tanhf(o2) + pre_off[pidx + 0];
                int idx = ((b*72 + i)*HH + y)*WW + x;
                float sim = pre_sim[idx];
                float msk = 1.f / (1.f + expf(-mr * sim));
                g_par[idx] = make_float4(dy, dx, msk, 0.f);
            }
        }
    }
}

// ---------------- kernel S: bilinear sample + dense 576-term reduce ---------
// grid (144, B), 256 threads, 16x16 tile, 64 accumulators (32 packed pairs).
// smem: ws[72][8][64] = 147456 B
__global__ void __launch_bounds__(256, 1)
k_sample(const float* __restrict__ weight,
         const float* __restrict__ bias,
         float* __restrict__ out) {
    extern __shared__ float ws[];
    int b    = blockIdx.y;
    int tile = blockIdx.x;
    int ty0  = (tile / 12) * 16;
    int tx0  = (tile % 12) * 16;
    int tid  = threadIdx.x;

    // weight[o][cin][kk] -> ws[(g*9+k)*8 + c][o]
    for (int m = tid; m < 72*8*64; m += 256) {
        int o = m & 63;
        int c = (m >> 6) & 7;
        int i = m >> 9;             // g*9 + k
        int k = i % 9, g = i / 9;
        ws[m] = weight[(o*CINC + g*8 + c)*KKC + k];
    }
    __syncthreads();

    int ty = tid >> 4, tx = tid & 15;
    int y = ty0 + ty, x = tx0 + tx;

    u64 acc[32];
    #pragma unroll
    for (int q = 0; q < 32; q++) acc[q] = 0ull;

    for (int g = 0; g < DGC; g++) {
        const float* xb = g_x0t + (size_t)(b*DGC + g) * HWC * CGC;
        for (int k = 0; k < KKC; k++) {
            int i = g*9 + k;
            float4 pr = g_par[((b*72 + i)*HH + y)*WW + x];
            float dy = pr.x, dx = pr.y, mk = pr.z;
            float py = (float)(y - 1 + k/3) + dy;
            float px = (float)(x - 1 + k%3) + dx;
            float y0f = floorf(py), x0f = floorf(px);
            float ly = py - y0f,   lx = px - x0f;
            int iy0 = (int)y0f, ix0 = (int)x0f;

            u64 sv2[4] = {0ull, 0ull, 0ull, 0ull};
            #pragma unroll
            for (int cy = 0; cy < 2; cy++) {
                int yy = iy0 + cy;
                if (yy < 0 || yy >= HH) continue;
                float wy = cy ? ly : (1.f - ly);
                #pragma unroll
                for (int cx = 0; cx < 2; cx++) {
                    int xx = ix0 + cx;
                    if (xx < 0 || xx >= WW) continue;
                    u64 wg2 = pk2(wy * (cx ? lx : (1.f - lx)));
                    const ulonglong2* p =
                        reinterpret_cast<const ulonglong2*>(xb + (size_t)(yy*WW + xx)*CGC);
                    ulonglong2 v0 = p[0];
                    ulonglong2 v1 = p[1];
                    fma2(sv2[0], wg2, v0.x);
                    fma2(sv2[1], wg2, v0.y);
                    fma2(sv2[2], wg2, v1.x);
                    fma2(sv2[3], wg2, v1.y);
                }
            }

            const float* wrow = ws + i*512;
            #pragma unroll
            for (int c = 0; c < 8; c++) {
                u64 h = sv2[c >> 1];
                float s = ((c & 1) ? hi32(h) : lo32(h)) * mk;
                u64 s2 = pk2(s);
                const ulonglong2* wp =
                    reinterpret_cast<const ulonglong2*>(wrow + c*64);
                #pragma unroll
                for (int q = 0; q < 16; q++) {
                    ulonglong2 w = wp[q];
                    fma2(acc[2*q],   s2, w.x);
                    fma2(acc[2*q+1], s2, w.y);
                }
            }
        }
    }

    #pragma unroll
    for (int q = 0; q < 32; q++) {
        out[((b*COUTC + 2*q)    *HH + y)*WW + x] = lo32(acc[q]) + bias[2*q];
        out[((b*COUTC + 2*q + 1)*HH + y)*WW + x] = hi32(acc[q]) + bias[2*q+1];
    }
}

// ---------------- launch ----------------------------------------------------
extern "C" void kernel_launch(void* const* d_in, const int* in_sizes, int n_in,
                              void* d_out, int out_size) {
    const float* x0      = (const float*)d_in[0];
    const float* x1      = (const float*)d_in[1];
    const float* pre_off = (const float*)d_in[2];
    const float* pre_sim = (const float*)d_in[3];
    const float* weight  = (const float*)d_in[4];
    const float* bias    = (const float*)d_in[5];
    const float* com_w   = (const float*)d_in[6];
    const float* com_b   = (const float*)d_in[7];
    float* out = (float*)d_out;

    cudaFuncSetAttribute(k_offsets, cudaFuncAttributeMaxDynamicSharedMemorySize, 221184);
    cudaFuncSetAttribute(k_sample,  cudaFuncAttributeMaxDynamicSharedMemorySize, 147456);

    int totalT = BD*DGC*HWC;
    k_transpose<<<(totalT + 255) / 256, 256>>>(x0);

    dim3 gridC(72, BD);
    k_offsets<<<gridC, 256, 221184>>>(x1, com_w, com_b, pre_off, pre_sim);
    dim3 gridS(144, BD);
    k_sample <<<gridS, 256, 147456>>>(weight, bias, out);
}